// round 3
// baseline (speedup 1.0000x reference)
#include <cuda_runtime.h>
#include <math.h>

#define POOLED   7
#define CHANNELS 256
#define H        50
#define W        50
#define SCALE    0.0625f

__global__ void __launch_bounds__(256)
roipool_kernel(const float* __restrict__ feat,
               const float* __restrict__ rois,
               float* __restrict__ out,
               int total)
{
    int idx = blockIdx.x * 256 + threadIdx.x;
    if (idx >= total) return;

    int pw = idx % POOLED;
    int ph = (idx / POOLED) % POOLED;
    int c  = (idx / (POOLED * POOLED)) & (CHANNELS - 1);
    int r  = idx / (POOLED * POOLED * CHANNELS);

    const float* roi = rois + r * 5;
    int   b  = (int)roi[0];
    // round-half-up; x*0.0625 and +0.5 are exact in f32 for this range
    float x1 = floorf(__fadd_rn(__fmul_rn(roi[1], SCALE), 0.5f));
    float y1 = floorf(__fadd_rn(__fmul_rn(roi[2], SCALE), 0.5f));
    float x2 = floorf(__fadd_rn(__fmul_rn(roi[3], SCALE), 0.5f));
    float y2 = floorf(__fadd_rn(__fmul_rn(roi[4], SCALE), 0.5f));

    float roi_w = fmaxf(__fadd_rn(__fadd_rn(x2, -x1), 1.0f), 1.0f);
    float roi_h = fmaxf(__fadd_rn(__fadd_rn(y2, -y1), 1.0f), 1.0f);

    // Match XLA-CPU fast-math: x/7 lowered to x * fl32(1/7)
    const float inv7 = 1.0f / 7.0f;  // 0x3E124925, compile-time round-to-nearest
    float bin_w = __fmul_rn(roi_w, inv7);
    float bin_h = __fmul_rn(roi_h, inv7);

    float pwf = (float)pw;
    float phf = (float)ph;

    float ws = fminf(fmaxf(__fadd_rn(floorf(__fmul_rn(pwf, bin_w)), x1), 0.0f), (float)W);
    float we = fminf(fmaxf(__fadd_rn(ceilf(__fmul_rn(__fadd_rn(pwf, 1.0f), bin_w)), x1), 0.0f), (float)W);
    float hs = fminf(fmaxf(__fadd_rn(floorf(__fmul_rn(phf, bin_h)), y1), 0.0f), (float)H);
    float he = fminf(fmaxf(__fadd_rn(ceilf(__fmul_rn(__fadd_rn(phf, 1.0f), bin_h)), y1), 0.0f), (float)H);

    int iws = (int)ws, iwe = (int)we;
    int ihs = (int)hs, ihe = (int)he;

    if (ihe <= ihs || iwe <= iws) {
        out[idx] = 0.0f;
        return;
    }

    const float* base = feat + ((size_t)(b * CHANNELS + c)) * (H * W);
    float m = -INFINITY;
    for (int h = ihs; h < ihe; ++h) {
        const float* row = base + h * W;
        for (int w = iws; w < iwe; ++w) {
            m = fmaxf(m, __ldg(row + w));
        }
    }
    out[idx] = m;
}

extern "C" void kernel_launch(void* const* d_in, const int* in_sizes, int n_in,
                              void* d_out, int out_size)
{
    const float* feat = (const float*)d_in[0];
    const float* rois = (const float*)d_in[1];
    float* out = (float*)d_out;

    int total = out_size; // 128 * 256 * 7 * 7 = 1,605,632
    int blocks = (total + 255) / 256;
    roipool_kernel<<<blocks, 256>>>(feat, rois, out, total);
}